// round 12
// baseline (speedup 1.0000x reference)
#include <cuda_runtime.h>
#include <cuda_fp16.h>
#include <stdint.h>

#define NN 4096
#define SB 4

#define CSPLIT   4                    // column split factor
#define ROWS_PB  16                   // rows per block (4 warps x 4 rows)
#define COLS_PB  (NN / CSPLIT)        // 1024
#define NRG      (NN / ROWS_PB)       // 256 row-groups
#define ITERS    (COLS_PB / 128)      // 8 warp-steps of 128 contiguous cols

// Scratch (allocation-free requirement => __device__ globals)
__device__ __align__(16) __half g_E [(size_t)NN * NN];   // exp(-C/eps)    [n][m]
__device__ __align__(16) __half g_Et[(size_t)NN * NN];   // transpose      [m][n]
__device__ __align__(16) float  g_u [SB * NN];
__device__ __align__(16) float  g_v [SB * NN];
__device__ __align__(16) float  g_part[CSPLIT * SB * NN]; // per-split partial sums
__device__ int g_cnt[NRG];                                // row-group arrival counters

// ---------------------------------------------------------------------------
// u0 = 1; counters = 0 (counters self-reset afterwards)
__global__ void init_u_kernel() {
    int i = blockIdx.x * blockDim.x + threadIdx.x;
    if (i < SB * NN) g_u[i] = 1.0f;
    if (i < NRG)     g_cnt[i] = 0;
}

// ---------------------------------------------------------------------------
// K = exp(-C/eps) in fp16, plus transposed copy (smem tile transpose).
__global__ __launch_bounds__(256) void prep_kernel(const float* __restrict__ C,
                                                   const float* __restrict__ eps_p) {
    __shared__ __half tile[32][33];
    const float scale = -1.4426950408889634f / eps_p[0];
    const int tx = threadIdx.x, ty = threadIdx.y;
    const int x  = blockIdx.x * 32 + tx;
    const int yb = blockIdx.y * 32;
#pragma unroll
    for (int j = 0; j < 32; j += 8) {
        int y = yb + ty + j;
        float c = __ldg(&C[(size_t)y * NN + x]);
        __half h = __float2half(exp2f(c * scale));
        g_E[(size_t)y * NN + x] = h;
        tile[ty + j][tx] = h;
    }
    __syncthreads();
    const int x2  = blockIdx.y * 32 + tx;
    const int yb2 = blockIdx.x * 32;
#pragma unroll
    for (int j = 0; j < 32; j += 8)
        g_Et[(size_t)(yb2 + ty + j) * NN + x2] = tile[tx][ty + j];
}

// ---------------------------------------------------------------------------
// One Sinkhorn half-step:  xout[s][n] = ab[s][n] / sum_m M[n][m] * xin[s][m]
//
// grid = 1024 blocks x 128 threads (CSPLIT=4): ~28 warps/SM of available work,
// reg cap 85 via __launch_bounds__(128,6) so ~6 blocks/SM stay resident.
// Each warp: 4 rows x 4 batches, 128 contiguous cols per step (4 cols/lane).
// u loaded as v2.b64 (direct f32x2 operands), E as v2.u32 with
// L1::no_allocate + L2::evict_last (E+Et stay L2-resident across passes).
__global__ __launch_bounds__(128, 6) void pass_kernel(int dir, const float* __restrict__ ab) {
    const __half* Mh   = dir ? g_Et : g_E;
    const float*  xin  = dir ? g_v  : g_u;
    float*        xout = dir ? g_u  : g_v;

    unsigned long long pol;
    asm("createpolicy.fractional.L2::evict_last.b64 %0, 1.0;" : "=l"(pol));

    const int rg   = blockIdx.x >> 2;      // row-group (0..255)
    const int q    = blockIdx.x & 3;       // column quarter
    const int warp = threadIdx.x >> 5;
    const int lane = threadIdx.x & 31;
    const int row0 = rg * ROWS_PB + warp * 4;
    const int col0 = q * COLS_PB;

    unsigned long long acc[4][4];
#pragma unroll
    for (int r = 0; r < 4; r++)
#pragma unroll
        for (int s = 0; s < 4; s++) acc[r][s] = 0ull;

#pragma unroll 2
    for (int it = 0; it < ITERS; ++it) {
        const int ci = col0 + it * 128 + lane * 4;   // 4 contiguous cols per lane

        // u: 4 batches x 4 cols, loaded directly as packed f32x2 pairs
        unsigned long long u01[SB], u23[SB];
#pragma unroll
        for (int s = 0; s < SB; s++)
            asm("ld.global.nc.v2.b64 {%0,%1}, [%2];"
                : "=l"(u01[s]), "=l"(u23[s]) : "l"(xin + s * NN + ci));

#pragma unroll
        for (int r = 0; r < 4; r++) {
            uint32_t ha, hb;   // 2x half2 = 4 E values for this row
            asm("ld.global.nc.L1::no_allocate.L2::cache_hint.v2.u32 {%0,%1}, [%2], %3;"
                : "=r"(ha), "=r"(hb)
                : "l"(Mh + (size_t)(row0 + r) * NN + ci), "l"(pol));
            float2 fa = __half22float2(*reinterpret_cast<const __half2*>(&ha));
            float2 fb = __half22float2(*reinterpret_cast<const __half2*>(&hb));
            unsigned long long e01, e23;
            asm("mov.b64 %0, {%1, %2};" : "=l"(e01) : "f"(fa.x), "f"(fa.y));
            asm("mov.b64 %0, {%1, %2};" : "=l"(e23) : "f"(fb.x), "f"(fb.y));
#pragma unroll
            for (int s = 0; s < SB; s++) {
                asm("fma.rn.f32x2 %0, %1, %2, %0;" : "+l"(acc[r][s]) : "l"(e01), "l"(u01[s]));
                asm("fma.rn.f32x2 %0, %1, %2, %0;" : "+l"(acc[r][s]) : "l"(e23), "l"(u23[s]));
            }
        }
    }

    // warp reduce each (row, batch); lane0 writes the partial for this split
#pragma unroll
    for (int r = 0; r < 4; r++) {
#pragma unroll
        for (int s = 0; s < 4; s++) {
            float lo, hi;
            asm("mov.b64 {%0, %1}, %2;" : "=f"(lo), "=f"(hi) : "l"(acc[r][s]));
            float t = lo + hi;
#pragma unroll
            for (int o = 16; o; o >>= 1) t += __shfl_down_sync(0xffffffffu, t, o);
            if (lane == 0)
                g_part[(q * SB + s) * NN + row0 + r] = t;
        }
    }

    // last-block-per-row-group does the deterministic combine + divide
    __shared__ int s_last;
    __threadfence();
    __syncthreads();
    if (threadIdx.x == 0) {
        int old = atomicAdd(&g_cnt[rg], 1);
        s_last = (old == CSPLIT - 1);
    }
    __syncthreads();
    if (s_last) {
        __threadfence();
        if (threadIdx.x < ROWS_PB * SB) {          // 64 outputs
            int nl = threadIdx.x >> 2;
            int s  = threadIdx.x & 3;
            int n  = rg * ROWS_PB + nl;
            float t = 0.0f;
#pragma unroll
            for (int qq = 0; qq < CSPLIT; qq++)    // fixed order => deterministic
                t += __ldcv(&g_part[(qq * SB + s) * NN + n]);
            xout[s * NN + n] = __ldg(&ab[s * NN + n]) / t;
        }
        if (threadIdx.x == 0) g_cnt[rg] = 0;       // self-clean for next pass
    }
}

// ---------------------------------------------------------------------------
// f = eps*log(v), g = eps*log(u)
__global__ void final_kernel(float* __restrict__ out, const float* __restrict__ eps_p) {
    int i = blockIdx.x * blockDim.x + threadIdx.x;
    float eps = eps_p[0];
    if (i < SB * NN) {
        out[i]           = eps * __logf(g_v[i]);  // f
        out[SB * NN + i] = eps * __logf(g_u[i]);  // g
    }
}

// ---------------------------------------------------------------------------
extern "C" void kernel_launch(void* const* d_in, const int* in_sizes, int n_in,
                              void* d_out, int out_size) {
    const float* alpha = (const float*)d_in[0];  // (4, 4096)
    const float* beta  = (const float*)d_in[1];  // (4, 4096)
    const float* C     = (const float*)d_in[2];  // (4096, 4096)
    const float* eps   = (const float*)d_in[3];  // scalar
    float* out = (float*)d_out;                  // f then g

    init_u_kernel<<<(SB * NN + 255) / 256, 256>>>();

    dim3 pb(32, 8), pg(NN / 32, NN / 32);
    prep_kernel<<<pg, pb>>>(C, eps);

    for (int it = 0; it < 10; it++) {
        pass_kernel<<<NRG * CSPLIT, 128>>>(0, alpha);  // v = alpha / (K  u)
        pass_kernel<<<NRG * CSPLIT, 128>>>(1, beta);   // u = beta  / (K^T v)
    }

    final_kernel<<<(SB * NN + 255) / 256, 256>>>(out, eps);
}

// round 13
// speedup vs baseline: 1.1053x; 1.1053x over previous
#include <cuda_runtime.h>
#include <cuda_fp16.h>
#include <stdint.h>

#define NN 4096
#define SB 4

#define CSPLIT   2                    // column split factor
#define ROWS_PB  16                   // rows per block (4 warps x 4 rows)
#define COLS_PB  (NN / CSPLIT)        // 2048
#define NRG      (NN / ROWS_PB)       // 256 row-groups
#define ITERS    (COLS_PB / 256)      // 8 warp-steps of 256 contiguous cols

// Scratch (allocation-free requirement => __device__ globals)
__device__ __align__(16) __half g_E [(size_t)NN * NN];   // exp(-C/eps)    [n][m]
__device__ __align__(16) __half g_Et[(size_t)NN * NN];   // transpose      [m][n]
__device__ __align__(16) float  g_u [SB * NN];
__device__ __align__(16) float  g_v [SB * NN];
__device__ __align__(16) float  g_part[CSPLIT * SB * NN]; // per-half partial sums
__device__ int g_cnt[NRG];                                // row-group arrival counters

// ---------------------------------------------------------------------------
// u0 = 1; counters = 0 (counters self-reset afterwards)
__global__ void init_u_kernel() {
    int i = blockIdx.x * blockDim.x + threadIdx.x;
    if (i < SB * NN) g_u[i] = 1.0f;
    if (i < NRG)     g_cnt[i] = 0;
}

// ---------------------------------------------------------------------------
// K = exp(-C/eps) in fp16, plus transposed copy (smem tile transpose).
__global__ __launch_bounds__(256) void prep_kernel(const float* __restrict__ C,
                                                   const float* __restrict__ eps_p) {
    __shared__ __half tile[32][33];
    const float scale = -1.4426950408889634f / eps_p[0];
    const int tx = threadIdx.x, ty = threadIdx.y;
    const int x  = blockIdx.x * 32 + tx;
    const int yb = blockIdx.y * 32;
#pragma unroll
    for (int j = 0; j < 32; j += 8) {
        int y = yb + ty + j;
        float c = __ldg(&C[(size_t)y * NN + x]);
        __half h = __float2half(exp2f(c * scale));
        g_E[(size_t)y * NN + x] = h;
        tile[ty + j][tx] = h;
    }
    __syncthreads();
    const int x2  = blockIdx.y * 32 + tx;
    const int yb2 = blockIdx.x * 32;
#pragma unroll
    for (int j = 0; j < 32; j += 8)
        g_Et[(size_t)(yb2 + ty + j) * NN + x2] = tile[tx][ty + j];
}

// ---------------------------------------------------------------------------
// One Sinkhorn half-step:  xout[s][n] = ab[s][n] / sum_m M[n][m] * xin[s][m]
//
// R10 shape (CSPLIT=2, 512 blocks x 128 thr, 4 blocks/SM) with a 2x wider
// warp-step: 256 contiguous cols per step, 8 cols/lane. E loaded as v4.u32
// (16B/lane, L1::no_allocate + L2::evict_last), u as 2x v2.b64 per batch
// (direct f32x2 operands). Doubles in-flight E bytes per warp to cover
// L2 latency at the LTS cap.
__global__ __launch_bounds__(128, 4) void pass_kernel(int dir, const float* __restrict__ ab) {
    const __half* Mh   = dir ? g_Et : g_E;
    const float*  xin  = dir ? g_v  : g_u;
    float*        xout = dir ? g_u  : g_v;

    unsigned long long pol;
    asm("createpolicy.fractional.L2::evict_last.b64 %0, 1.0;" : "=l"(pol));

    const int rg   = blockIdx.x >> 1;      // row-group (0..255)
    const int q    = blockIdx.x & 1;       // column half
    const int warp = threadIdx.x >> 5;
    const int lane = threadIdx.x & 31;
    const int row0 = rg * ROWS_PB + warp * 4;
    const int col0 = q * COLS_PB;

    unsigned long long acc[4][4];
#pragma unroll
    for (int r = 0; r < 4; r++)
#pragma unroll
        for (int s = 0; s < 4; s++) acc[r][s] = 0ull;

#pragma unroll 2
    for (int it = 0; it < ITERS; ++it) {
        const int ci = col0 + it * 256 + lane * 8;   // 8 contiguous cols per lane

        // u: 4 batches x 8 cols, loaded directly as packed f32x2 pairs
        unsigned long long up[SB][4];
#pragma unroll
        for (int s = 0; s < SB; s++) {
            asm("ld.global.nc.v2.b64 {%0,%1}, [%2];"
                : "=l"(up[s][0]), "=l"(up[s][1]) : "l"(xin + s * NN + ci));
            asm("ld.global.nc.v2.b64 {%0,%1}, [%2];"
                : "=l"(up[s][2]), "=l"(up[s][3]) : "l"(xin + s * NN + ci + 4));
        }

#pragma unroll
        for (int r = 0; r < 4; r++) {
            uint4 ev;   // 4x half2 = 8 E values for this row
            asm("ld.global.nc.L1::no_allocate.L2::cache_hint.v4.u32 {%0,%1,%2,%3}, [%4], %5;"
                : "=r"(ev.x), "=r"(ev.y), "=r"(ev.z), "=r"(ev.w)
                : "l"(Mh + (size_t)(row0 + r) * NN + ci), "l"(pol));
            uint32_t hw[4] = {ev.x, ev.y, ev.z, ev.w};
#pragma unroll
            for (int p = 0; p < 4; p++) {
                float2 f = __half22float2(*reinterpret_cast<const __half2*>(&hw[p]));
                unsigned long long e2;
                asm("mov.b64 %0, {%1, %2};" : "=l"(e2) : "f"(f.x), "f"(f.y));
#pragma unroll
                for (int s = 0; s < SB; s++)
                    asm("fma.rn.f32x2 %0, %1, %2, %0;" : "+l"(acc[r][s]) : "l"(e2), "l"(up[s][p]));
            }
        }
    }

    // warp reduce each (row, batch); lane0 writes the partial for this half
#pragma unroll
    for (int r = 0; r < 4; r++) {
#pragma unroll
        for (int s = 0; s < 4; s++) {
            float lo, hi;
            asm("mov.b64 {%0, %1}, %2;" : "=f"(lo), "=f"(hi) : "l"(acc[r][s]));
            float t = lo + hi;
#pragma unroll
            for (int o = 16; o; o >>= 1) t += __shfl_down_sync(0xffffffffu, t, o);
            if (lane == 0)
                g_part[(q * SB + s) * NN + row0 + r] = t;
        }
    }

    // last-block-per-row-group does the deterministic combine + divide
    __shared__ int s_last;
    __threadfence();
    __syncthreads();
    if (threadIdx.x == 0) {
        int old = atomicAdd(&g_cnt[rg], 1);
        s_last = (old == CSPLIT - 1);
    }
    __syncthreads();
    if (s_last) {
        __threadfence();
        if (threadIdx.x < ROWS_PB * SB) {          // 64 outputs
            int nl = threadIdx.x >> 2;
            int s  = threadIdx.x & 3;
            int n  = rg * ROWS_PB + nl;
            float t = __ldcv(&g_part[(0 * SB + s) * NN + n])
                    + __ldcv(&g_part[(1 * SB + s) * NN + n]);
            xout[s * NN + n] = __ldg(&ab[s * NN + n]) / t;
        }
        if (threadIdx.x == 0) g_cnt[rg] = 0;       // self-clean for next pass
    }
}

// ---------------------------------------------------------------------------
// f = eps*log(v), g = eps*log(u)
__global__ void final_kernel(float* __restrict__ out, const float* __restrict__ eps_p) {
    int i = blockIdx.x * blockDim.x + threadIdx.x;
    float eps = eps_p[0];
    if (i < SB * NN) {
        out[i]           = eps * __logf(g_v[i]);  // f
        out[SB * NN + i] = eps * __logf(g_u[i]);  // g
    }
}

// ---------------------------------------------------------------------------
extern "C" void kernel_launch(void* const* d_in, const int* in_sizes, int n_in,
                              void* d_out, int out_size) {
    const float* alpha = (const float*)d_in[0];  // (4, 4096)
    const float* beta  = (const float*)d_in[1];  // (4, 4096)
    const float* C     = (const float*)d_in[2];  // (4096, 4096)
    const float* eps   = (const float*)d_in[3];  // scalar
    float* out = (float*)d_out;                  // f then g

    init_u_kernel<<<(SB * NN + 255) / 256, 256>>>();

    dim3 pb(32, 8), pg(NN / 32, NN / 32);
    prep_kernel<<<pg, pb>>>(C, eps);

    for (int it = 0; it < 10; it++) {
        pass_kernel<<<NRG * CSPLIT, 128>>>(0, alpha);  // v = alpha / (K  u)
        pass_kernel<<<NRG * CSPLIT, 128>>>(1, beta);   // u = beta  / (K^T v)
    }

    final_kernel<<<(SB * NN + 255) / 256, 256>>>(out, eps);
}

// round 14
// speedup vs baseline: 1.1842x; 1.0714x over previous
#include <cuda_runtime.h>
#include <cuda_fp16.h>
#include <stdint.h>

#define NN 4096
#define SB 4

#define CSPLIT   2                    // column split factor
#define ROWS_PB  16                   // rows per block (4 warps x 4 rows)
#define COLS_PB  (NN / CSPLIT)        // 2048
#define NRG      (NN / ROWS_PB)       // 256 row-groups
#define ITERS    (COLS_PB / 128)      // 16 warp-steps of 128 contiguous cols
#define GRID     (NRG * CSPLIT)       // 512 blocks, all co-resident (<= 148*4)

// Scratch (allocation-free requirement => __device__ globals)
__device__ __align__(16) __half g_E [(size_t)NN * NN];   // exp(-C/eps)    [n][m]
__device__ __align__(16) __half g_Et[(size_t)NN * NN];   // transpose      [m][n]
__device__ __align__(16) float  g_u [SB * NN];
__device__ __align__(16) float  g_v [SB * NN];
__device__ __align__(16) float  g_part[CSPLIT * SB * NN]; // per-half partial sums
__device__ int g_cnt[NRG];              // row-group arrival counters (self-resetting)
__device__ unsigned g_bar;              // grid-barrier arrive counter (returns to 0)
__device__ volatile unsigned g_gen;     // grid-barrier generation (monotonic)

// ---------------------------------------------------------------------------
// Sense-reversing grid barrier. All GRID blocks are co-resident by
// construction. The trailing __threadfence() is load-bearing twice over:
// (a) acquire ordering, (b) gpu-scope fence emits CCTL.IVALL, invalidating
// this SM's L1 so .nc loads after the barrier can't see stale u/v lines.
__device__ __forceinline__ void grid_barrier() {
    __syncthreads();
    if (threadIdx.x == 0) {
        __threadfence();                      // publish this block's writes
        unsigned gen = g_gen;
        unsigned old = atomicAdd(&g_bar, 1);
        if (old == GRID - 1) {
            g_bar = 0;                        // safe: everyone has arrived
            __threadfence();
            g_gen = gen + 1;                  // release
        } else {
            while (g_gen == gen) __nanosleep(64);
        }
        __threadfence();                      // acquire + L1 invalidate
    }
    __syncthreads();
}

// ---------------------------------------------------------------------------
// K = exp(-C/eps) in fp16 + transpose. C is read with L2::evict_first so its
// 64 MB never displaces E/Et (which are written with L2::evict_last and stay
// resident across the entire replay -> passes never touch DRAM for E).
__global__ __launch_bounds__(256) void prep_kernel(const float* __restrict__ C,
                                                   const float* __restrict__ eps_p) {
    __shared__ __half tile[32][33];
    unsigned long long polF, polL;
    asm("createpolicy.fractional.L2::evict_first.b64 %0, 1.0;" : "=l"(polF));
    asm("createpolicy.fractional.L2::evict_last.b64 %0, 1.0;"  : "=l"(polL));
    const float scale = -1.4426950408889634f / eps_p[0];
    const int tx = threadIdx.x, ty = threadIdx.y;
    const int x  = blockIdx.x * 32 + tx;
    const int yb = blockIdx.y * 32;
#pragma unroll
    for (int j = 0; j < 32; j += 8) {
        int y = yb + ty + j;
        float c;
        asm("ld.global.nc.L2::cache_hint.f32 %0, [%1], %2;"
            : "=f"(c) : "l"(C + (size_t)y * NN + x), "l"(polF));
        __half h = __float2half(exp2f(c * scale));
        unsigned short hb = __half_as_ushort(h);
        asm volatile("st.global.L2::cache_hint.b16 [%0], %1, %2;"
                     :: "l"(&g_E[(size_t)y * NN + x]), "h"(hb), "l"(polL) : "memory");
        tile[ty + j][tx] = h;
    }
    __syncthreads();
    const int x2  = blockIdx.y * 32 + tx;
    const int yb2 = blockIdx.x * 32;
#pragma unroll
    for (int j = 0; j < 32; j += 8) {
        unsigned short hb = __half_as_ushort(tile[tx][ty + j]);
        asm volatile("st.global.L2::cache_hint.b16 [%0], %1, %2;"
                     :: "l"(&g_Et[(size_t)(yb2 + ty + j) * NN + x2]), "h"(hb), "l"(polL) : "memory");
    }
}

// ---------------------------------------------------------------------------
// Persistent Sinkhorn: init + 20 half-steps + finalize in ONE kernel.
// Per half-step: xout[s][n] = ab[s][n] / sum_m M[n][m] * xin[s][m]
// Loop body = R10's proven tile: 4 rows x 4 batches per warp, 128 contiguous
// cols per step (4/lane), u as v2.b64 (direct f32x2 operands), E as v2.u32
// with L1::no_allocate + L2::evict_last. Grid barrier between half-steps.
__global__ __launch_bounds__(128, 4) void sinkhorn_kernel(
    const float* __restrict__ alpha, const float* __restrict__ beta,
    const float* __restrict__ eps_p, float* __restrict__ out)
{
    __shared__ int s_last;
    const int tid  = threadIdx.x;
    const int warp = tid >> 5;
    const int lane = tid & 31;
    const int rg   = blockIdx.x >> 1;      // row-group (0..255)
    const int q    = blockIdx.x & 1;       // column half
    const int row0 = rg * ROWS_PB + warp * 4;
    const int col0 = q * COLS_PB;

    unsigned long long pol;
    asm("createpolicy.fractional.L2::evict_last.b64 %0, 1.0;" : "=l"(pol));

    // init: u = 1 (32 elements per block covers SB*NN = 16384)
    if (tid < 32) g_u[blockIdx.x * 32 + tid] = 1.0f;
    grid_barrier();

    for (int half = 0; half < 20; ++half) {
        const int dir = half & 1;
        const __half* Mh   = dir ? g_Et : g_E;
        const float*  xin  = dir ? g_v  : g_u;
        float*        xout = dir ? g_u  : g_v;
        const float*  ab   = dir ? beta : alpha;

        unsigned long long acc[4][4];
#pragma unroll
        for (int r = 0; r < 4; r++)
#pragma unroll
            for (int s = 0; s < 4; s++) acc[r][s] = 0ull;

#pragma unroll 2
        for (int it = 0; it < ITERS; ++it) {
            const int ci = col0 + it * 128 + lane * 4;   // 4 contiguous cols/lane

            unsigned long long u01[SB], u23[SB];
#pragma unroll
            for (int s = 0; s < SB; s++)
                asm("ld.global.nc.v2.b64 {%0,%1}, [%2];"
                    : "=l"(u01[s]), "=l"(u23[s]) : "l"(xin + s * NN + ci));

#pragma unroll
            for (int r = 0; r < 4; r++) {
                uint32_t ha, hb;   // 2x half2 = 4 E values for this row
                asm("ld.global.nc.L1::no_allocate.L2::cache_hint.v2.u32 {%0,%1}, [%2], %3;"
                    : "=r"(ha), "=r"(hb)
                    : "l"(Mh + (size_t)(row0 + r) * NN + ci), "l"(pol));
                float2 fa = __half22float2(*reinterpret_cast<const __half2*>(&ha));
                float2 fb = __half22float2(*reinterpret_cast<const __half2*>(&hb));
                unsigned long long e01, e23;
                asm("mov.b64 %0, {%1, %2};" : "=l"(e01) : "f"(fa.x), "f"(fa.y));
                asm("mov.b64 %0, {%1, %2};" : "=l"(e23) : "f"(fb.x), "f"(fb.y));
#pragma unroll
                for (int s = 0; s < SB; s++) {
                    asm("fma.rn.f32x2 %0, %1, %2, %0;" : "+l"(acc[r][s]) : "l"(e01), "l"(u01[s]));
                    asm("fma.rn.f32x2 %0, %1, %2, %0;" : "+l"(acc[r][s]) : "l"(e23), "l"(u23[s]));
                }
            }
        }

        // warp reduce each (row, batch); lane0 writes the partial for this half
#pragma unroll
        for (int r = 0; r < 4; r++) {
#pragma unroll
            for (int s = 0; s < 4; s++) {
                float lo, hi;
                asm("mov.b64 {%0, %1}, %2;" : "=f"(lo), "=f"(hi) : "l"(acc[r][s]));
                float t = lo + hi;
#pragma unroll
                for (int o = 16; o; o >>= 1) t += __shfl_down_sync(0xffffffffu, t, o);
                if (lane == 0)
                    g_part[(q * SB + s) * NN + row0 + r] = t;
            }
        }

        // last-block-per-row-group: deterministic combine + divide
        __threadfence();
        __syncthreads();
        if (tid == 0) {
            int old = atomicAdd(&g_cnt[rg], 1);
            s_last = (old == CSPLIT - 1);
        }
        __syncthreads();
        if (s_last) {
            __threadfence();
            if (tid < ROWS_PB * SB) {            // 64 outputs
                int nl = tid >> 2;
                int s  = tid & 3;
                int n  = rg * ROWS_PB + nl;
                float t = __ldcv(&g_part[(0 * SB + s) * NN + n])
                        + __ldcv(&g_part[(1 * SB + s) * NN + n]);
                xout[s * NN + n] = __ldg(&ab[s * NN + n]) / t;
            }
            if (tid == 0) g_cnt[rg] = 0;         // self-clean for next half
        }

        grid_barrier();
    }

    // finalize: f = eps*log(v), g = eps*log(u)
    const float eps = eps_p[0];
    const int i = blockIdx.x * 128 + tid;        // 65536 threads >= 16384
    if (i < SB * NN) {
        float v = __ldcv(&g_v[i]);
        float u = __ldcv(&g_u[i]);
        out[i]           = eps * __logf(v);      // f
        out[SB * NN + i] = eps * __logf(u);      // g
    }
}

// ---------------------------------------------------------------------------
extern "C" void kernel_launch(void* const* d_in, const int* in_sizes, int n_in,
                              void* d_out, int out_size) {
    const float* alpha = (const float*)d_in[0];  // (4, 4096)
    const float* beta  = (const float*)d_in[1];  // (4, 4096)
    const float* C     = (const float*)d_in[2];  // (4096, 4096)
    const float* eps   = (const float*)d_in[3];  // scalar
    float* out = (float*)d_out;                  // f then g

    dim3 pb(32, 8), pg(NN / 32, NN / 32);
    prep_kernel<<<pg, pb>>>(C, eps);

    sinkhorn_kernel<<<GRID, 128>>>(alpha, beta, eps, out);
}